// round 17
// baseline (speedup 1.0000x reference)
#include <cuda_runtime.h>
#include <cuda_bf16.h>
#include <math.h>
#include <stdint.h>

#define NB 4
#define ND 1024
#define NS 2048
#define NH 16
#define NTOK (NB*NS)   // 8192

// ---------------------------------------------------------------------------
// Scratch (allocation-free rule: device globals)
// ---------------------------------------------------------------------------
__device__ __nv_bfloat16 g_xh [(size_t)NTOK * ND];
__device__ __nv_bfloat16 g_xl [(size_t)NTOK * ND];
__device__ __nv_bfloat16 g_qh [(size_t)NTOK * ND];
__device__ __nv_bfloat16 g_ql [(size_t)NTOK * ND];
__device__ __nv_bfloat16 g_kh [(size_t)NTOK * ND];
__device__ __nv_bfloat16 g_kl [(size_t)NTOK * ND];
__device__ __nv_bfloat16 g_vh [(size_t)NTOK * ND];
__device__ __nv_bfloat16 g_vl [(size_t)NTOK * ND];
__device__ __nv_bfloat16 g_ath[(size_t)NTOK * ND];
__device__ __nv_bfloat16 g_atl[(size_t)NTOK * ND];
__device__ __nv_bfloat16 g_wh [(size_t)4 * ND * ND];
__device__ __nv_bfloat16 g_wl [(size_t)4 * ND * ND];

// ---------------------------------------------------------------------------
// PTX helpers (sm_80-level ISA only: works at compute_103 virtual arch)
// ---------------------------------------------------------------------------
__device__ __forceinline__ uint32_t smem_u32(const void* p) {
    return (uint32_t)__cvta_generic_to_shared(p);
}
__device__ __forceinline__ void cpa16(uint32_t saddr, const void* g) {
    asm volatile("cp.async.cg.shared.global [%0], [%1], 16;"
                 :: "r"(saddr), "l"(g) : "memory");
}
__device__ __forceinline__ void cpa_commit() {
    asm volatile("cp.async.commit_group;" ::: "memory");
}
template<int N>
__device__ __forceinline__ void cpa_wait() {
    asm volatile("cp.async.wait_group %0;" :: "n"(N) : "memory");
}
__device__ __forceinline__ void ldsm4(uint32_t& r0, uint32_t& r1,
                                      uint32_t& r2, uint32_t& r3, uint32_t a) {
    asm volatile("ldmatrix.sync.aligned.m8n8.x4.shared.b16 {%0,%1,%2,%3}, [%4];"
                 : "=r"(r0), "=r"(r1), "=r"(r2), "=r"(r3) : "r"(a));
}
__device__ __forceinline__ void ldsm4t(uint32_t& r0, uint32_t& r1,
                                       uint32_t& r2, uint32_t& r3, uint32_t a) {
    asm volatile("ldmatrix.sync.aligned.m8n8.x4.trans.shared.b16 {%0,%1,%2,%3}, [%4];"
                 : "=r"(r0), "=r"(r1), "=r"(r2), "=r"(r3) : "r"(a));
}
__device__ __forceinline__ void mma16816(float* c, const uint32_t* a,
                                         uint32_t b0, uint32_t b1) {
    asm volatile(
        "mma.sync.aligned.m16n8k16.row.col.f32.bf16.bf16.f32 "
        "{%0,%1,%2,%3}, {%4,%5,%6,%7}, {%8,%9}, {%0,%1,%2,%3};"
        : "+f"(c[0]), "+f"(c[1]), "+f"(c[2]), "+f"(c[3])
        : "r"(a[0]), "r"(a[1]), "r"(a[2]), "r"(a[3]), "r"(b0), "r"(b1));
}
__device__ __forceinline__ void split_bf16(float v, __nv_bfloat16& h, __nv_bfloat16& l) {
    h = __float2bfloat16(v);
    l = __float2bfloat16(v - __bfloat162float(h));
}
__device__ __forceinline__ void split2(float a, float b, uint32_t& hi, uint32_t& lo) {
    __nv_bfloat16 ha = __float2bfloat16(a), hb = __float2bfloat16(b);
    float ra = a - __bfloat162float(ha), rb = b - __bfloat162float(hb);
    __nv_bfloat162 H = __halves2bfloat162(ha, hb);
    __nv_bfloat162 L = __halves2bfloat162(__float2bfloat16(ra), __float2bfloat16(rb));
    hi = *reinterpret_cast<uint32_t*>(&H);
    lo = *reinterpret_cast<uint32_t*>(&L);
}

// ---------------------------------------------------------------------------
// Kernel 1: x[b,d,s] + PE(d,s) -> transposed bf16 hi/lo: g_xh/g_xl[(b*S+s)*D+d]
// ---------------------------------------------------------------------------
__global__ void pe_split_kernel(const float* __restrict__ x) {
    __shared__ float tile[32][33];
    int b  = blockIdx.z;
    int d0 = blockIdx.y * 32;
    int s0 = blockIdx.x * 32;
    int tx = threadIdx.x, ty = threadIdx.y;
    #pragma unroll
    for (int i = 0; i < 32; i += 8) {
        int d = d0 + ty + i;
        int s = s0 + tx;
        float v = x[(size_t)b * ND * NS + (size_t)d * NS + s];
        float base = (float)(d & ~1);
        float freq = __expf(base * (-9.210340371976184f / (float)ND));
        float ang  = (float)s * freq;
        v += (d & 1) ? cosf(ang) : sinf(ang);
        tile[ty + i][tx] = v;
    }
    __syncthreads();
    #pragma unroll
    for (int i = 0; i < 32; i += 8) {
        int s = s0 + ty + i;
        int d = d0 + tx;
        float v = tile[tx][ty + i];
        __nv_bfloat16 h, l;
        split_bf16(v, h, l);
        size_t o = ((size_t)b * NS + s) * ND + d;
        g_xh[o] = h;
        g_xl[o] = l;
    }
}

// ---------------------------------------------------------------------------
// Kernel 1b: weight split W (fp32 [N,K]) * scale -> hi/lo bf16
// ---------------------------------------------------------------------------
__global__ void wsplit_kernel(const float* __restrict__ w,
                              __nv_bfloat16* __restrict__ h,
                              __nv_bfloat16* __restrict__ l, float scale) {
    int i = (blockIdx.x * blockDim.x + threadIdx.x) * 4;
    float4 v = *(const float4*)(w + i);
    __nv_bfloat16 h0,h1,h2,h3,l0,l1,l2,l3;
    split_bf16(v.x*scale, h0, l0); split_bf16(v.y*scale, h1, l1);
    split_bf16(v.z*scale, h2, l2); split_bf16(v.w*scale, h3, l3);
    ((__nv_bfloat162*)(h + i))[0] = __halves2bfloat162(h0, h1);
    ((__nv_bfloat162*)(h + i))[1] = __halves2bfloat162(h2, h3);
    ((__nv_bfloat162*)(l + i))[0] = __halves2bfloat162(l0, l1);
    ((__nv_bfloat162*)(l + i))[1] = __halves2bfloat162(l2, l3);
}

// ---------------------------------------------------------------------------
// Kernel 2: bf16x3 GEMM via mma.sync (HMMA).  C = A*W^T + bias*bscale.
// 4-stage cp.async pipeline, BK=16, ONE __syncthreads per chunk.
// MODE 1: f32 out transposed to [B,D,S] via smem-staged coalesced stores.
// MODE 2: bf16 hi/lo pair outputs.
// ---------------------------------------------------------------------------
#define ROWB   48                       // bytes per smem row (16 bf16 + pad)
#define TILEB  (128 * ROWB)             // 6144 B
#define T_AH   0
#define T_AL   (1 * TILEB)
#define T_WH   (2 * TILEB)
#define T_WL   (3 * TILEB)
#define STAGEB (4 * TILEB)              // 24576 B
#define NSTAGE 4
#define GEMM_SMEM (NSTAGE * STAGEB)     // 98304 B  (>= 128*132*4 for MODE1 stage)

template<int MODE>
__global__ void __launch_bounds__(256, 2) tc_gemm_kernel(
    const __nv_bfloat16* __restrict__ Ah, const __nv_bfloat16* __restrict__ Al,
    const __nv_bfloat16* __restrict__ Wh, const __nv_bfloat16* __restrict__ Wl,
    const float* __restrict__ bias, float bscale, float* __restrict__ C,
    __nv_bfloat16* __restrict__ Ch, __nv_bfloat16* __restrict__ Cl)
{
    extern __shared__ __align__(128) char smem[];
    uint32_t sb = smem_u32(smem);
    int tid  = threadIdx.x;
    int lane = tid & 31;
    int wid  = tid >> 5;
    int col0 = blockIdx.x * 128;
    int row0 = blockIdx.y * 128;

    const char* gAh = (const char*)Ah;
    const char* gAl = (const char*)Al;
    const char* gWh = (const char*)Wh;
    const char* gWl = (const char*)Wl;

    int lr  = tid >> 1;           // 0..127
    int lch = tid & 1;            // 16B chunk within row
    auto load_chunk = [&](int kc, int buf) {
        int k0 = kc * 16;
        uint32_t sbb = sb + buf * STAGEB;
        uint32_t so  = (uint32_t)(lr * ROWB + lch * 16);
        size_t ga = ((size_t)(row0 + lr) * ND + k0 + lch * 8) * 2;
        size_t gw = ((size_t)(col0 + lr) * ND + k0 + lch * 8) * 2;
        cpa16(sbb + T_AH + so, gAh + ga);
        cpa16(sbb + T_AL + so, gAl + ga);
        cpa16(sbb + T_WH + so, gWh + gw);
        cpa16(sbb + T_WL + so, gWl + gw);
    };

    int wm = (wid & 3) * 32;
    int wn = (wid >> 2) * 64;
    int g  = lane >> 3;
    int gi = lane & 7;

    uint32_t a_off[2];
    #pragma unroll
    for (int mt = 0; mt < 2; mt++) {
        int r = wm + mt * 16 + (g & 1) * 8 + gi;
        a_off[mt] = (uint32_t)(r * ROWB + (g >> 1) * 16);
    }
    uint32_t b_off[4];
    #pragma unroll
    for (int np = 0; np < 4; np++) {
        int r = wn + np * 16 + (g >> 1) * 8 + gi;
        b_off[np] = (uint32_t)(r * ROWB + (g & 1) * 16);
    }

    float acc[2][8][4];
    #pragma unroll
    for (int mt = 0; mt < 2; mt++)
        #pragma unroll
        for (int nt = 0; nt < 8; nt++)
            #pragma unroll
            for (int e = 0; e < 4; e++) acc[mt][nt][e] = 0.f;

    #pragma unroll
    for (int p = 0; p < NSTAGE - 1; p++) { load_chunk(p, p); cpa_commit(); }

    const int NCHUNK = ND / 16;   // 64
    for (int kc = 0; kc < NCHUNK; kc++) {
        int buf = kc & (NSTAGE - 1);
        if (kc <= NCHUNK - 3)      cpa_wait<2>();
        else if (kc == NCHUNK - 2) cpa_wait<1>();
        else                       cpa_wait<0>();
        __syncthreads();

        uint32_t sbb = sb + buf * STAGEB;
        uint32_t ah[2][4], al[2][4];
        #pragma unroll
        for (int mt = 0; mt < 2; mt++) {
            ldsm4(ah[mt][0], ah[mt][1], ah[mt][2], ah[mt][3], sbb + T_AH + a_off[mt]);
            ldsm4(al[mt][0], al[mt][1], al[mt][2], al[mt][3], sbb + T_AL + a_off[mt]);
        }
        #pragma unroll
        for (int np = 0; np < 4; np++) {
            uint32_t bh0, bh1, bh2, bh3, bl0, bl1, bl2, bl3;
            ldsm4(bh0, bh1, bh2, bh3, sbb + T_WH + b_off[np]);
            ldsm4(bl0, bl1, bl2, bl3, sbb + T_WL + b_off[np]);
            #pragma unroll
            for (int mt = 0; mt < 2; mt++) {
                mma16816(acc[mt][np*2+0], ah[mt], bh0, bh1);
                mma16816(acc[mt][np*2+1], ah[mt], bh2, bh3);
                mma16816(acc[mt][np*2+0], ah[mt], bl0, bl1);
                mma16816(acc[mt][np*2+1], ah[mt], bl2, bl3);
                mma16816(acc[mt][np*2+0], al[mt], bh0, bh1);
                mma16816(acc[mt][np*2+1], al[mt], bh2, bh3);
            }
        }

        if (kc + NSTAGE - 1 < NCHUNK) {
            load_chunk(kc + NSTAGE - 1, (kc + NSTAGE - 1) & (NSTAGE - 1));
            cpa_commit();
        }
    }

    int cr = lane >> 2;
    int cc = (lane & 3) * 2;
    if (MODE == 1) {
        // stage fp32 into smem as [col][s] (pad 132), then coalesced col stores
        __syncthreads();
        float* smf = (float*)smem;
        #pragma unroll
        for (int nt = 0; nt < 8; nt++) {
            int colL = wn + nt * 8 + cc;
            float b0 = __ldg(&bias[col0 + colL]) * bscale;
            float b1 = __ldg(&bias[col0 + colL + 1]) * bscale;
            #pragma unroll
            for (int mt = 0; mt < 2; mt++) {
                int sL = wm + mt * 16 + cr;
                smf[(colL    ) * 132 + sL    ] = acc[mt][nt][0] + b0;
                smf[(colL + 1) * 132 + sL    ] = acc[mt][nt][1] + b1;
                smf[(colL    ) * 132 + sL + 8] = acc[mt][nt][2] + b0;
                smf[(colL + 1) * 132 + sL + 8] = acc[mt][nt][3] + b1;
            }
        }
        __syncthreads();
        int bb  = row0 >> 11;
        int s0i = row0 & (NS - 1);
        #pragma unroll
        for (int i = 0; i < 16; i++) {
            int colL = wid * 16 + i;
            float4 v = *(float4*)&smf[colL * 132 + 4 * lane];
            *(float4*)&C[((size_t)bb * ND + col0 + colL) * NS + s0i + 4 * lane] = v;
        }
    } else {
        #pragma unroll
        for (int nt = 0; nt < 8; nt++) {
            int col = col0 + wn + nt * 8 + cc;
            float b0 = __ldg(&bias[col]) * bscale;
            float b1 = __ldg(&bias[col + 1]) * bscale;
            #pragma unroll
            for (int mt = 0; mt < 2; mt++) {
                int row = row0 + wm + mt * 16 + cr;
                float v00 = acc[mt][nt][0] + b0;
                float v01 = acc[mt][nt][1] + b1;
                float v10 = acc[mt][nt][2] + b0;
                float v11 = acc[mt][nt][3] + b1;
                uint32_t h0, l0, h1, l1;
                split2(v00, v01, h0, l0);
                split2(v10, v11, h1, l1);
                size_t o0 = (size_t)row * ND + col;
                size_t o1 = (size_t)(row + 8) * ND + col;
                *(uint32_t*)&Ch[o0] = h0;
                *(uint32_t*)&Cl[o0] = l0;
                *(uint32_t*)&Ch[o1] = h1;
                *(uint32_t*)&Cl[o1] = l1;
            }
        }
    }
}

// ---------------------------------------------------------------------------
// Kernel 3: flash attention via mma.sync, hi/lo bf16 both GEMMs. (unchanged)
// ---------------------------------------------------------------------------
#define AT_ROW  72
#define AT_TILE (64 * AT_ROW * 2)
#define A_KH    0
#define A_KL    (1 * AT_TILE)
#define A_VH    (2 * AT_TILE)
#define A_VL    (3 * AT_TILE)
#define A_STAGE (4 * AT_TILE)
#define ATT_SMEM (2 * A_STAGE)           // 73728 B

__global__ void __launch_bounds__(256, 2) mma_attn_kernel() {
    extern __shared__ __align__(128) char smem[];
    uint32_t sb = smem_u32(smem);
    int b   = blockIdx.z, h = blockIdx.y;
    int q0g = blockIdx.x * 128;
    int tid = threadIdx.x;
    int lane = tid & 31;
    int wid  = tid >> 5;
    size_t hoff = (size_t)h * 64;
    int g  = lane >> 3;
    int gi = lane & 7;

    {
        int r  = tid >> 1;
        int c0 = (tid & 1) * 4;
        #pragma unroll
        for (int t = 0; t < 4; t++) {
            int ch = c0 + t;
            size_t go = ((size_t)(b * NS + q0g + r)) * ND + hoff + ch * 8;
            uint32_t so = (uint32_t)((r * AT_ROW + ch * 8) * 2);
            cpa16(sb + so,                 (const char*)&g_qh[go]);
            cpa16(sb + 128*AT_ROW*2 + so,  (const char*)&g_ql[go]);
        }
        cpa_commit();
        cpa_wait<0>();
    }
    __syncthreads();

    uint32_t qfh[4][4], qfl[4][4];
    {
        int arow = 16 * wid + (lane & 15);
        int acol = (lane >> 4) * 8;
        #pragma unroll
        for (int s = 0; s < 4; s++) {
            uint32_t ao = (uint32_t)((arow * AT_ROW + s * 16 + acol) * 2);
            ldsm4(qfh[s][0], qfh[s][1], qfh[s][2], qfh[s][3], sb + ao);
            ldsm4(qfl[s][0], qfl[s][1], qfl[s][2], qfl[s][3],
                  sb + 128*AT_ROW*2 + ao);
        }
    }
    __syncthreads();

    auto load_kv = [&](int kt, int buf) {
        int r  = tid >> 2;
        int c0 = (tid & 3) * 2;
        uint32_t sbb = sb + buf * A_STAGE;
        #pragma unroll
        for (int t = 0; t < 2; t++) {
            int ch = c0 + t;
            size_t go = ((size_t)(b * NS + kt * 64 + r)) * ND + hoff + ch * 8;
            uint32_t so = (uint32_t)((r * AT_ROW + ch * 8) * 2);
            cpa16(sbb + A_KH + so, (const char*)&g_kh[go]);
            cpa16(sbb + A_KL + so, (const char*)&g_kl[go]);
            cpa16(sbb + A_VH + so, (const char*)&g_vh[go]);
            cpa16(sbb + A_VL + so, (const char*)&g_vl[go]);
        }
    };

    uint32_t kb_off[4][4];
    #pragma unroll
    for (int s = 0; s < 4; s++)
        #pragma unroll
        for (int np = 0; np < 4; np++)
            kb_off[s][np] = (uint32_t)(((np * 16 + (g >> 1) * 8 + gi) * AT_ROW
                                        + s * 16 + (g & 1) * 8) * 2);
    uint32_t vb_off[4][4];
    #pragma unroll
    for (int t = 0; t < 4; t++)
        #pragma unroll
        for (int up = 0; up < 4; up++)
            vb_off[t][up] = (uint32_t)(((t * 16 + (g & 1) * 8 + gi) * AT_ROW
                                        + (2 * up + (g >> 1)) * 8) * 2);

    float m0r = -1e30f, m1r = -1e30f, l0r = 0.f, l1r = 0.f;
    float accO[8][4];
    #pragma unroll
    for (int dt = 0; dt < 8; dt++)
        #pragma unroll
        for (int e = 0; e < 4; e++) accO[dt][e] = 0.f;

    load_kv(0, 0);
    cpa_commit();

    const int NKT = NS / 64;   // 32
    for (int kt = 0; kt < NKT; kt++) {
        int buf = kt & 1;
        if (kt + 1 < NKT) {
            load_kv(kt + 1, buf ^ 1);
            cpa_commit();
            cpa_wait<1>();
        } else {
            cpa_wait<0>();
        }
        __syncthreads();
        uint32_t kb = sb + buf * A_STAGE;

        float sv[8][4];
        #pragma unroll
        for (int nt = 0; nt < 8; nt++)
            #pragma unroll
            for (int e = 0; e < 4; e++) sv[nt][e] = 0.f;

        #pragma unroll
        for (int s = 0; s < 4; s++) {
            #pragma unroll
            for (int np = 0; np < 4; np++) {
                uint32_t bh0, bh1, bh2, bh3, bl0, bl1, bl2, bl3;
                ldsm4(bh0, bh1, bh2, bh3, kb + A_KH + kb_off[s][np]);
                ldsm4(bl0, bl1, bl2, bl3, kb + A_KL + kb_off[s][np]);
                mma16816(sv[np*2+0], qfh[s], bh0, bh1);
                mma16816(sv[np*2+1], qfh[s], bh2, bh3);
                mma16816(sv[np*2+0], qfh[s], bl0, bl1);
                mma16816(sv[np*2+1], qfh[s], bl2, bl3);
                mma16816(sv[np*2+0], qfl[s], bh0, bh1);
                mma16816(sv[np*2+1], qfl[s], bh2, bh3);
            }
        }

        float mt0 = -1e30f, mt1 = -1e30f;
        #pragma unroll
        for (int nt = 0; nt < 8; nt++) {
            mt0 = fmaxf(mt0, fmaxf(sv[nt][0], sv[nt][1]));
            mt1 = fmaxf(mt1, fmaxf(sv[nt][2], sv[nt][3]));
        }
        mt0 = fmaxf(mt0, __shfl_xor_sync(0xffffffffu, mt0, 1));
        mt0 = fmaxf(mt0, __shfl_xor_sync(0xffffffffu, mt0, 2));
        mt1 = fmaxf(mt1, __shfl_xor_sync(0xffffffffu, mt1, 1));
        mt1 = fmaxf(mt1, __shfl_xor_sync(0xffffffffu, mt1, 2));
        float m0n = fmaxf(m0r, mt0), m1n = fmaxf(m1r, mt1);
        float c0 = __expf(m0r - m0n), c1 = __expf(m1r - m1n);
        float ls0 = 0.f, ls1 = 0.f;
        #pragma unroll
        for (int nt = 0; nt < 8; nt++) {
            sv[nt][0] = __expf(sv[nt][0] - m0n);
            sv[nt][1] = __expf(sv[nt][1] - m0n);
            sv[nt][2] = __expf(sv[nt][2] - m1n);
            sv[nt][3] = __expf(sv[nt][3] - m1n);
            ls0 += sv[nt][0] + sv[nt][1];
            ls1 += sv[nt][2] + sv[nt][3];
        }
        ls0 += __shfl_xor_sync(0xffffffffu, ls0, 1);
        ls0 += __shfl_xor_sync(0xffffffffu, ls0, 2);
        ls1 += __shfl_xor_sync(0xffffffffu, ls1, 1);
        ls1 += __shfl_xor_sync(0xffffffffu, ls1, 2);
        l0r = l0r * c0 + ls0;
        l1r = l1r * c1 + ls1;
        m0r = m0n; m1r = m1n;
        #pragma unroll
        for (int dt = 0; dt < 8; dt++) {
            accO[dt][0] *= c0; accO[dt][1] *= c0;
            accO[dt][2] *= c1; accO[dt][3] *= c1;
        }

        uint32_t pah[4][4], pal[4][4];
        #pragma unroll
        for (int t = 0; t < 4; t++) {
            split2(sv[2*t  ][0], sv[2*t  ][1], pah[t][0], pal[t][0]);
            split2(sv[2*t  ][2], sv[2*t  ][3], pah[t][1], pal[t][1]);
            split2(sv[2*t+1][0], sv[2*t+1][1], pah[t][2], pal[t][2]);
            split2(sv[2*t+1][2], sv[2*t+1][3], pah[t][3], pal[t][3]);
        }

        #pragma unroll
        for (int t = 0; t < 4; t++) {
            #pragma unroll
            for (int up = 0; up < 4; up++) {
                uint32_t vh0, vh1, vh2, vh3, vl0, vl1, vl2, vl3;
                ldsm4t(vh0, vh1, vh2, vh3, kb + A_VH + vb_off[t][up]);
                ldsm4t(vl0, vl1, vl2, vl3, kb + A_VL + vb_off[t][up]);
                mma16816(accO[2*up+0], pah[t], vh0, vh1);
                mma16816(accO[2*up+1], pah[t], vh2, vh3);
                mma16816(accO[2*up+0], pah[t], vl0, vl1);
                mma16816(accO[2*up+1], pah[t], vl2, vl3);
                mma16816(accO[2*up+0], pal[t], vh0, vh1);
                mma16816(accO[2*up+1], pal[t], vh2, vh3);
            }
        }
        __syncthreads();
    }

    float inv0 = 1.f / l0r, inv1 = 1.f / l1r;
    int r0 = q0g + 16 * wid + (lane >> 2);
    int cb = 2 * (lane & 3);
    #pragma unroll
    for (int dt = 0; dt < 8; dt++) {
        int col = dt * 8 + cb;
        float v00 = accO[dt][0] * inv0, v01 = accO[dt][1] * inv0;
        float v10 = accO[dt][2] * inv1, v11 = accO[dt][3] * inv1;
        uint32_t h0, l0, h1, l1;
        split2(v00, v01, h0, l0);
        split2(v10, v11, h1, l1);
        size_t o0 = ((size_t)(b * NS) + r0) * ND + hoff + col;
        size_t o1 = o0 + (size_t)8 * ND;
        *(uint32_t*)&g_ath[o0] = h0;
        *(uint32_t*)&g_atl[o0] = l0;
        *(uint32_t*)&g_ath[o1] = h1;
        *(uint32_t*)&g_atl[o1] = l1;
    }
}

// ---------------------------------------------------------------------------
extern "C" void kernel_launch(void* const* d_in, const int* in_sizes, int n_in,
                              void* d_out, int out_size) {
    const float* x  = (const float*)d_in[0];
    const float* Wq = (const float*)d_in[1];
    const float* bq = (const float*)d_in[2];
    const float* Wk = (const float*)d_in[3];
    const float* bk = (const float*)d_in[4];
    const float* Wv = (const float*)d_in[5];
    const float* bv = (const float*)d_in[6];
    const float* Wo = (const float*)d_in[7];
    const float* bo = (const float*)d_in[8];
    float* out = (float*)d_out;

    __nv_bfloat16 *xh, *xl, *qh, *ql, *kh, *kl, *vh, *vl, *ath, *atl, *wh, *wl;
    cudaGetSymbolAddress((void**)&xh,  g_xh);
    cudaGetSymbolAddress((void**)&xl,  g_xl);
    cudaGetSymbolAddress((void**)&qh,  g_qh);
    cudaGetSymbolAddress((void**)&ql,  g_ql);
    cudaGetSymbolAddress((void**)&kh,  g_kh);
    cudaGetSymbolAddress((void**)&kl,  g_kl);
    cudaGetSymbolAddress((void**)&vh,  g_vh);
    cudaGetSymbolAddress((void**)&vl,  g_vl);
    cudaGetSymbolAddress((void**)&ath, g_ath);
    cudaGetSymbolAddress((void**)&atl, g_atl);
    cudaGetSymbolAddress((void**)&wh,  g_wh);
    cudaGetSymbolAddress((void**)&wl,  g_wl);

    const size_t WSZ = (size_t)ND * ND;

    cudaFuncSetAttribute(tc_gemm_kernel<1>,
                         cudaFuncAttributeMaxDynamicSharedMemorySize, GEMM_SMEM);
    cudaFuncSetAttribute(tc_gemm_kernel<2>,
                         cudaFuncAttributeMaxDynamicSharedMemorySize, GEMM_SMEM);
    cudaFuncSetAttribute(mma_attn_kernel,
                         cudaFuncAttributeMaxDynamicSharedMemorySize, ATT_SMEM);

    // PE + transpose + bf16 split
    pe_split_kernel<<<dim3(NS/32, ND/32, NB), dim3(32, 8)>>>(x);

    // weight splits (Wq folded with 1/sqrt(head_dim) = 0.125)
    wsplit_kernel<<<ND*ND/1024, 256>>>(Wq, wh + 0*WSZ, wl + 0*WSZ, 0.125f);
    wsplit_kernel<<<ND*ND/1024, 256>>>(Wk, wh + 1*WSZ, wl + 1*WSZ, 1.0f);
    wsplit_kernel<<<ND*ND/1024, 256>>>(Wv, wh + 2*WSZ, wl + 2*WSZ, 1.0f);
    wsplit_kernel<<<ND*ND/1024, 256>>>(Wo, wh + 3*WSZ, wl + 3*WSZ, 1.0f);

    // Q/K/V projections (HMMA) -> bf16 hi/lo outputs
    dim3 ggrid(ND/128, NTOK/128);
    tc_gemm_kernel<2><<<ggrid, 256, GEMM_SMEM>>>(xh, xl, wh + 0*WSZ, wl + 0*WSZ,
                                                 bq, 0.125f, nullptr, qh, ql);
    tc_gemm_kernel<2><<<ggrid, 256, GEMM_SMEM>>>(xh, xl, wh + 1*WSZ, wl + 1*WSZ,
                                                 bk, 1.0f, nullptr, kh, kl);
    tc_gemm_kernel<2><<<ggrid, 256, GEMM_SMEM>>>(xh, xl, wh + 2*WSZ, wl + 2*WSZ,
                                                 bv, 1.0f, nullptr, vh, vl);

    // attention (HMMA, hi/lo both GEMMs)
    mma_attn_kernel<<<dim3(NS/128, NH, NB), 256, ATT_SMEM>>>();

    // O-projection with fused [B,D,S] transpose epilogue
    tc_gemm_kernel<1><<<ggrid, 256, GEMM_SMEM>>>(ath, atl, wh + 3*WSZ, wl + 3*WSZ,
                                                 bo, 1.0f, out, nullptr, nullptr);
}